// round 4
// baseline (speedup 1.0000x reference)
#include <cuda_runtime.h>

// entmax-1.5 over rows: p_i = max(z_i - tau, 0)^2 where z = (mask? s : -1e4)/2 - max,
// and tau is the unique root of sum_i max(z_i - tau,0)^2 = 1, bracketed in [-1, 0]
// after the shift (max element alone contributes exactly 1 at tau = -1).
// Bisection (30 iters) replaces the reference's sort exactly (same root).
//
// Mask is materialized as int32 on device (harness dtype set is f32/i32/bf16),
// so it is read via int4, NOT bytes.

constexpr int COLS    = 4096;
constexpr int THREADS = 256;
constexpr int PER     = COLS / THREADS;  // 16 elements per thread
constexpr int VEC     = PER / 4;         // 4 float4 chunks per thread

__global__ __launch_bounds__(THREADS) void entmax15_kernel(
    const float* __restrict__ scores,
    const int* __restrict__ mask,
    float* __restrict__ out)
{
    const size_t row = blockIdx.x;
    const float* s = scores + row * COLS;
    const int*   m = mask   + row * COLS;
    float* o = out + row * COLS;

    const int t    = threadIdx.x;
    const int wid  = t >> 5;
    const int lane = t & 31;

    // ---- Load 16 elements per thread, apply mask + /2, track local max ----
    float z[PER];
    float lmax = -3.402823e38f;
#pragma unroll
    for (int c = 0; c < VEC; ++c) {
        const int idx = c * (THREADS * 4) + t * 4;   // coalesced float4 / int4
        float4 v  = __ldcs(reinterpret_cast<const float4*>(s + idx));
        int4   mm = __ldcs(reinterpret_cast<const int4*>(m + idx));
        float z0 = (mm.x ? v.x : -1.0e4f) * 0.5f;
        float z1 = (mm.y ? v.y : -1.0e4f) * 0.5f;
        float z2 = (mm.z ? v.z : -1.0e4f) * 0.5f;
        float z3 = (mm.w ? v.w : -1.0e4f) * 0.5f;
        z[c * 4 + 0] = z0;
        z[c * 4 + 1] = z1;
        z[c * 4 + 2] = z2;
        z[c * 4 + 3] = z3;
        lmax = fmaxf(lmax, fmaxf(fmaxf(z0, z1), fmaxf(z2, z3)));
    }

    // ---- Block max reduction ----
    __shared__ float sh_max[THREADS / 32];
#pragma unroll
    for (int off = 16; off > 0; off >>= 1)
        lmax = fmaxf(lmax, __shfl_xor_sync(0xffffffffu, lmax, off));
    if (lane == 0) sh_max[wid] = lmax;
    __syncthreads();
    float rmax = sh_max[0];
#pragma unroll
    for (int i = 1; i < THREADS / 32; ++i) rmax = fmaxf(rmax, sh_max[i]);

#pragma unroll
    for (int i = 0; i < PER; ++i) z[i] -= rmax;

    // ---- Bisection on tau in [-1, 0] ----
    // f(tau) = sum max(z - tau, 0)^2 is strictly decreasing; f(-1) >= 1, f(0) = 0.
    __shared__ float sh_sum[2][THREADS / 32];  // double-buffered: 1 sync/iter
    float lo = -1.0f, hi = 0.0f;

#pragma unroll 1
    for (int it = 0; it < 30; ++it) {
        const float tau = 0.5f * (lo + hi);
        float acc = 0.0f;
#pragma unroll
        for (int i = 0; i < PER; ++i) {
            float d = fmaxf(z[i] - tau, 0.0f);
            acc = fmaf(d, d, acc);
        }
#pragma unroll
        for (int off = 16; off > 0; off >>= 1)
            acc += __shfl_xor_sync(0xffffffffu, acc, off);

        const int buf = it & 1;
        if (lane == 0) sh_sum[buf][wid] = acc;
        __syncthreads();
        float tot = sh_sum[buf][0];
#pragma unroll
        for (int i = 1; i < THREADS / 32; ++i) tot += sh_sum[buf][i];

        if (tot >= 1.0f) lo = tau; else hi = tau;
        // no second sync needed: next iter writes the other buffer;
        // reads of buf at iter it complete before the sync at it+1, which
        // precedes the next write to buf at it+2.
    }
    const float tau = 0.5f * (lo + hi);

    // ---- Write p = max(z - tau, 0)^2 with streaming stores ----
#pragma unroll
    for (int c = 0; c < VEC; ++c) {
        const int idx = c * (THREADS * 4) + t * 4;
        float d0 = fmaxf(z[c * 4 + 0] - tau, 0.0f);
        float d1 = fmaxf(z[c * 4 + 1] - tau, 0.0f);
        float d2 = fmaxf(z[c * 4 + 2] - tau, 0.0f);
        float d3 = fmaxf(z[c * 4 + 3] - tau, 0.0f);
        float4 p;
        p.x = d0 * d0; p.y = d1 * d1; p.z = d2 * d2; p.w = d3 * d3;
        __stcs(reinterpret_cast<float4*>(o + idx), p);
    }
}

extern "C" void kernel_launch(void* const* d_in, const int* in_sizes, int n_in,
                              void* d_out, int out_size) {
    const float* scores = (const float*)d_in[0];
    const int*   mask   = (const int*)d_in[1];
    float* out = (float*)d_out;
    const int rows = in_sizes[0] / COLS;
    entmax15_kernel<<<rows, THREADS>>>(scores, mask, out);
}

// round 5
// speedup vs baseline: 1.2287x; 1.2287x over previous
#include <cuda_runtime.h>

// entmax-1.5 over rows: p_i = max(z_i - tau, 0)^2 with z = (mask? s : -1e4)*0.5 - rowmax,
// tau = root of sum max(z - tau,0)^2 = 1, which lies in [-1, 0] after the shift.
//
// KEY: any element with z <= -1 contributes exactly 0 for all tau in [-1,0]
// (z - tau <= 0), so only elements with z > -1 (~90 of 4096 for this data)
// participate in the bisection. They are compacted into shared memory once;
// the 24 bisection iterations then run on ~1 register value per thread
// instead of 16, removing ~95% of the FFMA/FMNMX work that bound round 4.

constexpr int COLS    = 4096;
constexpr int THREADS = 256;
constexpr int PER     = COLS / THREADS;  // 16
constexpr int VEC     = PER / 4;         // 4
constexpr int NWARP   = THREADS / 32;    // 8
constexpr int NITER   = 24;              // dtau = 2^-25 ~ 3e-8, << 1e-3 tol

__global__ __launch_bounds__(THREADS) void entmax15_kernel(
    const float* __restrict__ scores,
    const int* __restrict__ mask,
    float* __restrict__ out)
{
    __shared__ float buf[COLS];          // compacted active z values
    __shared__ int   cnt;
    __shared__ float sh_max[NWARP];
    __shared__ float sh_red[2][NWARP];   // double-buffered: 1 sync per iter

    const size_t row = blockIdx.x;
    const float* s = scores + row * COLS;
    const int*   m = mask   + row * COLS;
    float* o = out + row * COLS;

    const int t    = threadIdx.x;
    const int wid  = t >> 5;
    const int lane = t & 31;

    // ---- Load 16 elements/thread, apply mask + *0.5, track local max ----
    float z[PER];
    float lmax = -3.402823e38f;
#pragma unroll
    for (int c = 0; c < VEC; ++c) {
        const int idx = c * (THREADS * 4) + t * 4;
        float4 v  = __ldcs(reinterpret_cast<const float4*>(s + idx));
        int4   mm = __ldcs(reinterpret_cast<const int4*>(m + idx));
        float z0 = (mm.x ? v.x : -1.0e4f) * 0.5f;
        float z1 = (mm.y ? v.y : -1.0e4f) * 0.5f;
        float z2 = (mm.z ? v.z : -1.0e4f) * 0.5f;
        float z3 = (mm.w ? v.w : -1.0e4f) * 0.5f;
        z[c*4+0] = z0; z[c*4+1] = z1; z[c*4+2] = z2; z[c*4+3] = z3;
        lmax = fmaxf(lmax, fmaxf(fmaxf(z0, z1), fmaxf(z2, z3)));
    }

    // ---- Block max ----
#pragma unroll
    for (int off = 16; off > 0; off >>= 1)
        lmax = fmaxf(lmax, __shfl_xor_sync(0xffffffffu, lmax, off));
    if (lane == 0) sh_max[wid] = lmax;
    if (t == 0) cnt = 0;
    __syncthreads();
    float rmax = sh_max[0];
#pragma unroll
    for (int i = 1; i < NWARP; ++i) rmax = fmaxf(rmax, sh_max[i]);

#pragma unroll
    for (int i = 0; i < PER; ++i) z[i] -= rmax;

    // ---- Compact active elements (z > -1) into shared ----
#pragma unroll
    for (int i = 0; i < PER; ++i) {
        if (z[i] > -1.0f) {
            int p = atomicAdd(&cnt, 1);   // warp-aggregated by compiler
            buf[p] = z[i];
        }
    }
    __syncthreads();
    const int n = cnt;

    // ---- Bisection on tau in [-1, 0] over active set only ----
    float lo = -1.0f, hi = 0.0f;

    if (n <= THREADS) {
        // fast path: one active value per thread, held in a register
        float v = (t < n) ? buf[t] : -2.0f;  // sentinel: v - tau < 0 always
#pragma unroll 1
        for (int it = 0; it < NITER; ++it) {
            const float tau = 0.5f * (lo + hi);
            float d = fmaxf(v - tau, 0.0f);
            float acc = d * d;
#pragma unroll
            for (int off = 16; off > 0; off >>= 1)
                acc += __shfl_xor_sync(0xffffffffu, acc, off);
            const int b = it & 1;
            if (lane == 0) sh_red[b][wid] = acc;
            __syncthreads();
            float tot = sh_red[b][0];
#pragma unroll
            for (int i = 1; i < NWARP; ++i) tot += sh_red[b][i];
            if (tot >= 1.0f) lo = tau; else hi = tau;
        }
    } else {
        // generic path (rare): loop active set from shared
#pragma unroll 1
        for (int it = 0; it < NITER; ++it) {
            const float tau = 0.5f * (lo + hi);
            float acc = 0.0f;
            for (int i = t; i < n; i += THREADS) {
                float d = fmaxf(buf[i] - tau, 0.0f);
                acc = fmaf(d, d, acc);
            }
#pragma unroll
            for (int off = 16; off > 0; off >>= 1)
                acc += __shfl_xor_sync(0xffffffffu, acc, off);
            const int b = it & 1;
            if (lane == 0) sh_red[b][wid] = acc;
            __syncthreads();
            float tot = sh_red[b][0];
#pragma unroll
            for (int i = 1; i < NWARP; ++i) tot += sh_red[b][i];
            if (tot >= 1.0f) lo = tau; else hi = tau;
        }
    }
    const float tau = 0.5f * (lo + hi);

    // ---- Write p = max(z - tau, 0)^2 with streaming stores ----
#pragma unroll
    for (int c = 0; c < VEC; ++c) {
        const int idx = c * (THREADS * 4) + t * 4;
        float d0 = fmaxf(z[c*4+0] - tau, 0.0f);
        float d1 = fmaxf(z[c*4+1] - tau, 0.0f);
        float d2 = fmaxf(z[c*4+2] - tau, 0.0f);
        float d3 = fmaxf(z[c*4+3] - tau, 0.0f);
        float4 p;
        p.x = d0*d0; p.y = d1*d1; p.z = d2*d2; p.w = d3*d3;
        __stcs(reinterpret_cast<float4*>(o + idx), p);
    }
}

extern "C" void kernel_launch(void* const* d_in, const int* in_sizes, int n_in,
                              void* d_out, int out_size) {
    const float* scores = (const float*)d_in[0];
    const int*   mask   = (const int*)d_in[1];
    float* out = (float*)d_out;
    const int rows = in_sizes[0] / COLS;
    entmax15_kernel<<<rows, THREADS>>>(scores, mask, out);
}

// round 6
// speedup vs baseline: 2.0705x; 1.6851x over previous
#include <cuda_runtime.h>

// entmax-1.5 over rows. z = (mask? s : -1e4)*0.5 - rowmax; tau = root of
// sum max(z-tau,0)^2 = 1, bracketed in [-1,0] after the shift.
// Only elements with z > -1 (~90/4096) can contribute; they are compacted to
// shared once. ONE warp then runs 10 bisections on register-resident actives
// (no block barriers) and finishes with the exact fixed-support closed form
//   tau = (S1 - sqrt(S1^2 - k(S2-1)))/k  over support {z > lo},
// identical to the reference's per-support formula. Support misclassification
// within the 2^-11 bracket perturbs tau by O(w^2) ~ 2e-7 — far inside tol.

constexpr int COLS    = 4096;
constexpr int THREADS = 256;
constexpr int PER     = COLS / THREADS;  // 16
constexpr int VEC     = PER / 4;         // 4
constexpr int NWARP   = THREADS / 32;    // 8
constexpr int NB      = 10;              // bisection iterations
constexpr int CAP     = 128;             // register fast-path active cap (4/lane)

__device__ __forceinline__ float warp_sum(float v) {
#pragma unroll
    for (int off = 16; off > 0; off >>= 1)
        v += __shfl_xor_sync(0xffffffffu, v, off);
    return v;   // all lanes hold the total
}

__global__ __launch_bounds__(THREADS) void entmax15_kernel(
    const float* __restrict__ scores,
    const int* __restrict__ mask,
    float* __restrict__ out)
{
    __shared__ float buf[COLS];      // compacted active z values
    __shared__ int   cnt;
    __shared__ float sh_max[NWARP];
    __shared__ float sh_tau;

    const size_t row = blockIdx.x;
    const float* s = scores + row * COLS;
    const int*   m = mask   + row * COLS;
    float* o = out + row * COLS;

    const int t    = threadIdx.x;
    const int wid  = t >> 5;
    const int lane = t & 31;

    // ---- Load 16 elements/thread, apply mask + *0.5, local max ----
    float z[PER];
    float lmax = -3.402823e38f;
#pragma unroll
    for (int c = 0; c < VEC; ++c) {
        const int idx = c * (THREADS * 4) + t * 4;
        float4 v  = __ldcs(reinterpret_cast<const float4*>(s + idx));
        int4   mm = __ldcs(reinterpret_cast<const int4*>(m + idx));
        float z0 = (mm.x ? v.x : -1.0e4f) * 0.5f;
        float z1 = (mm.y ? v.y : -1.0e4f) * 0.5f;
        float z2 = (mm.z ? v.z : -1.0e4f) * 0.5f;
        float z3 = (mm.w ? v.w : -1.0e4f) * 0.5f;
        z[c*4+0] = z0; z[c*4+1] = z1; z[c*4+2] = z2; z[c*4+3] = z3;
        lmax = fmaxf(lmax, fmaxf(fmaxf(z0, z1), fmaxf(z2, z3)));
    }

    // ---- Block max ----
#pragma unroll
    for (int off = 16; off > 0; off >>= 1)
        lmax = fmaxf(lmax, __shfl_xor_sync(0xffffffffu, lmax, off));
    if (lane == 0) sh_max[wid] = lmax;
    if (t == 0) cnt = 0;
    __syncthreads();
    float rmax = sh_max[0];
#pragma unroll
    for (int i = 1; i < NWARP; ++i) rmax = fmaxf(rmax, sh_max[i]);

#pragma unroll
    for (int i = 0; i < PER; ++i) z[i] -= rmax;

    // ---- Compact actives (z > -1) into shared ----
#pragma unroll
    for (int i = 0; i < PER; ++i) {
        if (z[i] > -1.0f) {
            int p = atomicAdd(&cnt, 1);      // warp-aggregated
            buf[p] = z[i];
        }
    }
    __syncthreads();

    // ---- Warp 0 solves for tau alone; others wait at the barrier below ----
    if (wid == 0) {
        const int n = cnt;                   // >= 1 (max elem z = 0 > -1)
        float lo = -1.0f, hi = 0.0f;

        if (n <= CAP) {
            // fast path: 4 actives per lane in registers
            float v[4];
#pragma unroll
            for (int j = 0; j < 4; ++j) {
                int i = lane + 32 * j;
                v[j] = (i < n) ? buf[i] : -2.0f;   // sentinel: never in support
            }
#pragma unroll 1
            for (int it = 0; it < NB; ++it) {
                const float tau = 0.5f * (lo + hi);
                float acc = 0.0f;
#pragma unroll
                for (int j = 0; j < 4; ++j) {
                    float d = fmaxf(v[j] - tau, 0.0f);
                    acc = fmaf(d, d, acc);
                }
                float tot = warp_sum(acc);
                if (tot >= 1.0f) lo = tau; else hi = tau;
            }
            // closed form over support {z > lo}
            float k = 0.0f, S1 = 0.0f, S2 = 0.0f;
#pragma unroll
            for (int j = 0; j < 4; ++j) {
                if (v[j] > lo) { k += 1.0f; S1 += v[j]; S2 = fmaf(v[j], v[j], S2); }
            }
            k = warp_sum(k); S1 = warp_sum(S1); S2 = warp_sum(S2);
            float disc = fmaxf(fmaf(S1, S1, -k * (S2 - 1.0f)), 0.0f);
            float tau = (S1 - sqrtf(disc)) / k;
            if (lane == 0) sh_tau = tau;
        } else {
            // generic path (rare): loop actives from shared
#pragma unroll 1
            for (int it = 0; it < NB; ++it) {
                const float tau = 0.5f * (lo + hi);
                float acc = 0.0f;
                for (int i = lane; i < n; i += 32) {
                    float d = fmaxf(buf[i] - tau, 0.0f);
                    acc = fmaf(d, d, acc);
                }
                float tot = warp_sum(acc);
                if (tot >= 1.0f) lo = tau; else hi = tau;
            }
            float k = 0.0f, S1 = 0.0f, S2 = 0.0f;
            for (int i = lane; i < n; i += 32) {
                float v = buf[i];
                if (v > lo) { k += 1.0f; S1 += v; S2 = fmaf(v, v, S2); }
            }
            k = warp_sum(k); S1 = warp_sum(S1); S2 = warp_sum(S2);
            float disc = fmaxf(fmaf(S1, S1, -k * (S2 - 1.0f)), 0.0f);
            float tau = (S1 - sqrtf(disc)) / k;
            if (lane == 0) sh_tau = tau;
        }
    }
    __syncthreads();
    const float tau = sh_tau;

    // ---- Write p = max(z - tau, 0)^2 with streaming stores ----
#pragma unroll
    for (int c = 0; c < VEC; ++c) {
        const int idx = c * (THREADS * 4) + t * 4;
        float d0 = fmaxf(z[c*4+0] - tau, 0.0f);
        float d1 = fmaxf(z[c*4+1] - tau, 0.0f);
        float d2 = fmaxf(z[c*4+2] - tau, 0.0f);
        float d3 = fmaxf(z[c*4+3] - tau, 0.0f);
        float4 p;
        p.x = d0*d0; p.y = d1*d1; p.z = d2*d2; p.w = d3*d3;
        __stcs(reinterpret_cast<float4*>(o + idx), p);
    }
}

extern "C" void kernel_launch(void* const* d_in, const int* in_sizes, int n_in,
                              void* d_out, int out_size) {
    const float* scores = (const float*)d_in[0];
    const int*   mask   = (const int*)d_in[1];
    float* out = (float*)d_out;
    const int rows = in_sizes[0] / COLS;
    entmax15_kernel<<<rows, THREADS>>>(scores, mask, out);
}

// round 7
// speedup vs baseline: 2.1368x; 1.0320x over previous
#include <cuda_runtime.h>

// entmax-1.5 over rows. zbuf holds z = (mask? s : -1e4)*0.5 (UNshifted) in shared;
// the max-shift is folded: active iff z > rmax-1, solve on v = z - rmax,
// final p = max(z - (rmax + tau), 0)^2.
// tau = root of sum max(v - tau,0)^2 = 1, bracketed in [-1,0].
// Only ~90/4096 elements are active; warp 0 runs 10 bisections on
// register-resident actives + exact fixed-support closed form:
//   tau = (S1 - sqrt(S1^2 - k(S2-1)))/k over support {v > lo}.
// z lives in SHARED, not registers -> regs ~30, 8 CTAs/SM, loads overlap.

constexpr int COLS    = 4096;
constexpr int THREADS = 256;
constexpr int PER     = COLS / THREADS;  // 16
constexpr int VEC     = PER / 4;         // 4
constexpr int NWARP   = THREADS / 32;    // 8
constexpr int NB      = 10;              // bisection iterations
constexpr int CAP     = 128;             // register fast path (4/lane)
constexpr int ACAP    = 1024;            // abuf capacity (mid path)

__device__ __forceinline__ float warp_sum(float v) {
#pragma unroll
    for (int off = 16; off > 0; off >>= 1)
        v += __shfl_xor_sync(0xffffffffu, v, off);
    return v;
}

__global__ __launch_bounds__(THREADS, 8) void entmax15_kernel(
    const float* __restrict__ scores,
    const int* __restrict__ mask,
    float* __restrict__ out)
{
    __shared__ float zbuf[COLS];     // full row of z (unshifted)
    __shared__ float abuf[ACAP];     // compacted actives (shifted: v = z - rmax)
    __shared__ int   cnt;
    __shared__ float sh_max[NWARP];
    __shared__ float sh_tau;

    const size_t row = blockIdx.x;
    const float* s = scores + row * COLS;
    const int*   m = mask   + row * COLS;
    float* o = out + row * COLS;

    const int t    = threadIdx.x;
    const int wid  = t >> 5;
    const int lane = t & 31;

    // ---- Load, mask, *0.5 -> shared; track local max in regs ----
    float lmax = -3.402823e38f;
#pragma unroll
    for (int c = 0; c < VEC; ++c) {
        const int idx = c * (THREADS * 4) + t * 4;
        float4 v  = __ldcs(reinterpret_cast<const float4*>(s + idx));
        int4   mm = __ldcs(reinterpret_cast<const int4*>(m + idx));
        float4 zz;
        zz.x = (mm.x ? v.x : -1.0e4f) * 0.5f;
        zz.y = (mm.y ? v.y : -1.0e4f) * 0.5f;
        zz.z = (mm.z ? v.z : -1.0e4f) * 0.5f;
        zz.w = (mm.w ? v.w : -1.0e4f) * 0.5f;
        *reinterpret_cast<float4*>(zbuf + idx) = zz;
        lmax = fmaxf(lmax, fmaxf(fmaxf(zz.x, zz.y), fmaxf(zz.z, zz.w)));
    }

    // ---- Block max ----
#pragma unroll
    for (int off = 16; off > 0; off >>= 1)
        lmax = fmaxf(lmax, __shfl_xor_sync(0xffffffffu, lmax, off));
    if (lane == 0) sh_max[wid] = lmax;
    if (t == 0) cnt = 0;
    __syncthreads();
    float rmax = sh_max[0];
#pragma unroll
    for (int i = 1; i < NWARP; ++i) rmax = fmaxf(rmax, sh_max[i]);
    const float thr = rmax - 1.0f;   // active iff z > thr

    // ---- Compact actives from shared (store shifted v = z - rmax) ----
#pragma unroll
    for (int c = 0; c < VEC; ++c) {
        const int idx = c * (THREADS * 4) + t * 4;
        float4 zz = *reinterpret_cast<const float4*>(zbuf + idx);
#pragma unroll
        for (int j = 0; j < 4; ++j) {
            float zv = (&zz.x)[j];
            if (zv > thr) {
                int p = atomicAdd(&cnt, 1);          // warp-aggregated
                if (p < ACAP) abuf[p] = zv - rmax;
            }
        }
    }
    __syncthreads();

    // ---- Warp 0 solves tau ----
    if (wid == 0) {
        const int n = cnt;   // >= 1 (max element has v = 0 > -1)
        float lo = -1.0f, hi = 0.0f;
        float tau;

        if (n <= CAP) {
            float v[4];
#pragma unroll
            for (int j = 0; j < 4; ++j) {
                int i = lane + 32 * j;
                v[j] = (i < n) ? abuf[i] : -2.0f;    // sentinel
            }
#pragma unroll 1
            for (int it = 0; it < NB; ++it) {
                const float tm = 0.5f * (lo + hi);
                float acc = 0.0f;
#pragma unroll
                for (int j = 0; j < 4; ++j) {
                    float d = fmaxf(v[j] - tm, 0.0f);
                    acc = fmaf(d, d, acc);
                }
                if (warp_sum(acc) >= 1.0f) lo = tm; else hi = tm;
            }
            float k = 0.0f, S1 = 0.0f, S2 = 0.0f;
#pragma unroll
            for (int j = 0; j < 4; ++j)
                if (v[j] > lo) { k += 1.0f; S1 += v[j]; S2 = fmaf(v[j], v[j], S2); }
            k = warp_sum(k); S1 = warp_sum(S1); S2 = warp_sum(S2);
            float disc = fmaxf(fmaf(S1, S1, -k * (S2 - 1.0f)), 0.0f);
            tau = (S1 - sqrtf(disc)) / k;
        } else if (n <= ACAP) {
#pragma unroll 1
            for (int it = 0; it < NB; ++it) {
                const float tm = 0.5f * (lo + hi);
                float acc = 0.0f;
                for (int i = lane; i < n; i += 32) {
                    float d = fmaxf(abuf[i] - tm, 0.0f);
                    acc = fmaf(d, d, acc);
                }
                if (warp_sum(acc) >= 1.0f) lo = tm; else hi = tm;
            }
            float k = 0.0f, S1 = 0.0f, S2 = 0.0f;
            for (int i = lane; i < n; i += 32) {
                float v = abuf[i];
                if (v > lo) { k += 1.0f; S1 += v; S2 = fmaf(v, v, S2); }
            }
            k = warp_sum(k); S1 = warp_sum(S1); S2 = warp_sum(S2);
            float disc = fmaxf(fmaf(S1, S1, -k * (S2 - 1.0f)), 0.0f);
            tau = (S1 - sqrtf(disc)) / k;
        } else {
            // pathological: scan the full row in shared
#pragma unroll 1
            for (int it = 0; it < NB; ++it) {
                const float tm = 0.5f * (lo + hi);
                float acc = 0.0f;
                for (int i = lane; i < COLS; i += 32) {
                    float d = fmaxf((zbuf[i] - rmax) - tm, 0.0f);
                    acc = fmaf(d, d, acc);
                }
                if (warp_sum(acc) >= 1.0f) lo = tm; else hi = tm;
            }
            float k = 0.0f, S1 = 0.0f, S2 = 0.0f;
            for (int i = lane; i < COLS; i += 32) {
                float v = zbuf[i] - rmax;
                if (v > lo) { k += 1.0f; S1 += v; S2 = fmaf(v, v, S2); }
            }
            k = warp_sum(k); S1 = warp_sum(S1); S2 = warp_sum(S2);
            float disc = fmaxf(fmaf(S1, S1, -k * (S2 - 1.0f)), 0.0f);
            tau = (S1 - sqrtf(disc)) / k;
        }
        if (lane == 0) sh_tau = tau;
    }
    __syncthreads();
    const float taup = sh_tau + rmax;    // p = max(z - taup, 0)^2

    // ---- Store p from shared ----
#pragma unroll
    for (int c = 0; c < VEC; ++c) {
        const int idx = c * (THREADS * 4) + t * 4;
        float4 zz = *reinterpret_cast<const float4*>(zbuf + idx);
        float d0 = fmaxf(zz.x - taup, 0.0f);
        float d1 = fmaxf(zz.y - taup, 0.0f);
        float d2 = fmaxf(zz.z - taup, 0.0f);
        float d3 = fmaxf(zz.w - taup, 0.0f);
        float4 p;
        p.x = d0*d0; p.y = d1*d1; p.z = d2*d2; p.w = d3*d3;
        __stcs(reinterpret_cast<float4*>(o + idx), p);
    }
}

extern "C" void kernel_launch(void* const* d_in, const int* in_sizes, int n_in,
                              void* d_out, int out_size) {
    const float* scores = (const float*)d_in[0];
    const int*   mask   = (const int*)d_in[1];
    float* out = (float*)d_out;
    const int rows = in_sizes[0] / COLS;
    entmax15_kernel<<<rows, THREADS>>>(scores, mask, out);
}